// round 5
// baseline (speedup 1.0000x reference)
#include <cuda_runtime.h>

// FoldNd (col2im): B=16, C=64, K=3, H=W=128, PAD=1, STR=1, DIL=1
// Gather form, vec4 per thread, warp = one output row, shuffles for the
// +/-1 boundary elements. All 9 LDG.128 are made UNCONDITIONAL by clamping
// the row index and masking the contribution with an FFMA by {0,1} — this
// lets ptxas front-batch the full load group (MLP_p1 = 9).

namespace {
constexpr int H = 128;
constexpr int W = 128;
constexpr int PLANE = H * W;            // 16384
constexpr int NOUT = 16 * 64 * H * W;   // 16,777,216
constexpr int NVEC = NOUT / 4;          // 4,194,304
}

__global__ void __launch_bounds__(256) fold_vec4_batch_kernel(
    const float* __restrict__ in, float* __restrict__ out)
{
    int v = blockIdx.x * blockDim.x + threadIdx.x;   // grid covers NVEC exactly

    int lane = v & 31;
    int w0 = lane << 2;              // 0,4,...,124 (warp spans one row)
    int h  = (v >> 5) & (H - 1);
    int bc = v >> 12;                // b*64 + c

    const float* base = in + (long long)bc * 9 * PLANE;

    float4 A[3], Bv[3], Cv[3];
    float  m[3];

    // Issue all 9 vector loads up front (clamped rows; invalid kh masked later).
    #pragma unroll
    for (int kh = 0; kh < 3; ++kh) {
        int lh = h + 1 - kh;
        m[kh] = ((unsigned)lh < (unsigned)H) ? 1.0f : 0.0f;
        int lhc = lh < 0 ? 0 : (lh > H - 1 ? H - 1 : lh);
        const float* r0 = base + (kh * 3) * PLANE + lhc * W;
        A[kh]  = __ldg(reinterpret_cast<const float4*>(r0 + w0));
        Bv[kh] = __ldg(reinterpret_cast<const float4*>(r0 + PLANE + w0));
        Cv[kh] = __ldg(reinterpret_cast<const float4*>(r0 + 2 * PLANE + w0));
    }

    float4 acc = make_float4(0.f, 0.f, 0.f, 0.f);

    #pragma unroll
    for (int kh = 0; kh < 3; ++kh) {
        // a4  = r0[w0+4] = next lane's A.x   (lane 31: lw=128 -> 0)
        // cm1 = r2[w0-1] = prev lane's Cv.w  (lane 0:  lw=-1  -> 0)
        float a4  = __shfl_down_sync(0xFFFFFFFFu, A[kh].x, 1);
        float cm1 = __shfl_up_sync(0xFFFFFFFFu, Cv[kh].w, 1);
        if (lane == 31) a4  = 0.f;
        if (lane == 0)  cm1 = 0.f;

        // output w0+j: kw0 -> elem(w0+j+1), kw1 -> elem(w0+j), kw2 -> elem(w0+j-1)
        acc.x = fmaf(m[kh], A[kh].y + Bv[kh].x + cm1,      acc.x);
        acc.y = fmaf(m[kh], A[kh].z + Bv[kh].y + Cv[kh].x, acc.y);
        acc.z = fmaf(m[kh], A[kh].w + Bv[kh].z + Cv[kh].y, acc.z);
        acc.w = fmaf(m[kh], a4      + Bv[kh].w + Cv[kh].z, acc.w);
    }

    __stcs(reinterpret_cast<float4*>(out) + v, acc);
}

extern "C" void kernel_launch(void* const* d_in, const int* in_sizes, int n_in,
                              void* d_out, int out_size)
{
    const float* in = (const float*)d_in[0];
    float* out = (float*)d_out;
    const int threads = 256;
    const int blocks = NVEC / threads;   // exact: 16384 blocks
    fold_vec4_batch_kernel<<<blocks, threads>>>(in, out);
}

// round 6
// speedup vs baseline: 1.0073x; 1.0073x over previous
#include <cuda_runtime.h>

// FoldNd (col2im): B=16, C=64, K=3, H=W=128, PAD=1, STR=1, DIL=1
// Gather form, vec4 per thread, warp = one output row, boundary elements via
// warp shuffle (zero scalar loads). Input is pure read-once streaming ->
// __ldcs (evict-first) reads; output write-once -> __stcs stores.
// 512-thread blocks to reduce CTA dispatch overhead.

namespace {
constexpr int H = 128;
constexpr int W = 128;
constexpr int PLANE = H * W;            // 16384
constexpr int NOUT = 16 * 64 * H * W;   // 16,777,216
constexpr int NVEC = NOUT / 4;          // 4,194,304
}

__global__ void __launch_bounds__(512) fold_vec4_stream_kernel(
    const float* __restrict__ in, float* __restrict__ out)
{
    int v = blockIdx.x * blockDim.x + threadIdx.x;   // grid covers NVEC exactly

    int lane = v & 31;
    int w0 = lane << 2;              // 0,4,...,124 (warp spans one row)
    int h  = (v >> 5) & (H - 1);
    int bc = v >> 12;                // b*64 + c

    const float* base = in + (long long)bc * 9 * PLANE;

    float4 acc = make_float4(0.f, 0.f, 0.f, 0.f);

    #pragma unroll
    for (int kh = 0; kh < 3; ++kh) {
        int lh = h + 1 - kh;         // warp-uniform predicate
        if ((unsigned)lh < (unsigned)H) {
            const float* r0 = base + (kh * 3 + 0) * PLANE + lh * W; // kw=0
            const float* r1 = r0 + PLANE;                            // kw=1
            const float* r2 = r1 + PLANE;                            // kw=2

            float4 A  = __ldcs(reinterpret_cast<const float4*>(r0 + w0));
            float4 Bv = __ldcs(reinterpret_cast<const float4*>(r1 + w0));
            float4 Cv = __ldcs(reinterpret_cast<const float4*>(r2 + w0));

            // a4  = r0[w0+4] = next lane's A.x   (lane 31: lw=128 -> 0)
            // cm1 = r2[w0-1] = prev lane's Cv.w  (lane 0:  lw=-1  -> 0)
            float a4  = __shfl_down_sync(0xFFFFFFFFu, A.x, 1);
            float cm1 = __shfl_up_sync(0xFFFFFFFFu, Cv.w, 1);
            if (lane == 31) a4  = 0.f;
            if (lane == 0)  cm1 = 0.f;

            // output w0+j: kw0 -> elem(w0+j+1), kw1 -> elem(w0+j), kw2 -> elem(w0+j-1)
            acc.x += A.y + Bv.x + cm1;
            acc.y += A.z + Bv.y + Cv.x;
            acc.z += A.w + Bv.z + Cv.y;
            acc.w += a4  + Bv.w + Cv.z;
        }
    }

    __stcs(reinterpret_cast<float4*>(out) + v, acc);
}

extern "C" void kernel_launch(void* const* d_in, const int* in_sizes, int n_in,
                              void* d_out, int out_size)
{
    const float* in = (const float*)d_in[0];
    float* out = (float*)d_out;
    const int threads = 512;
    const int blocks = NVEC / threads;   // exact: 8192 blocks
    fold_vec4_stream_kernel<<<blocks, threads>>>(in, out);
}